// round 15
// baseline (speedup 1.0000x reference)
#include <cuda_runtime.h>
#include <cuda_fp16.h>
#include <cstdint>

#define B_    16
#define CIN   512
#define COUT  512
#define DLAT  512
#define Hs    64
#define Ws    64
#define NPIX  (Hs*Ws)

#define LIN_COEF  0.04419417382415922f    // 1/sqrt(512)
#define CONV_COEF 0.014731391274719742f   // 1/sqrt(512*9)

// ---------------- device scratch (no allocation allowed) ----------------
__device__ float g_mod[B_ * CIN];
__device__ float g_sig[B_ * COUT];
__device__ float g_wsqT[CIN * COUT];               // [i][o]
__device__ __half g_xh[(size_t)B_ * NPIX * CIN];   // NHWC, fp16(x*mod)
__device__ __half g_wh[9 * COUT * CIN];            // [tap][o][i] fp16

__device__ __forceinline__ uint32_t smem_u32(const void* p) {
    uint32_t a;
    asm("{ .reg .u64 t; cvta.to.shared.u64 t, %1; cvt.u32.u64 %0, t; }"
        : "=r"(a) : "l"(p));
    return a;
}

// ============================================================
// KP1: style (bid<32) + wsq tiled-transpose (bid<288) + w->fp16 (bid<800)
// ============================================================
__global__ __launch_bounds__(256) void kp1(
    const float* __restrict__ w, const float* __restrict__ sw,
    const float* __restrict__ sb, const float* __restrict__ cw)
{
    int bid = blockIdx.x;
    if (bid < 32) {
        __shared__ float s_sw[16][DLAT + 1];
        int i0 = bid * 16;
        for (int idx = threadIdx.x; idx < 16 * DLAT; idx += 256) {
            int r = idx / DLAT, d = idx % DLAT;
            s_sw[r][d] = sw[(i0 + r) * DLAT + d];
        }
        __syncthreads();
        int t = threadIdx.x;
        int b = t >> 4, il = t & 15;
        const float* wb = w + b * DLAT;
        float acc = 0.f;
        for (int d = 0; d < DLAT; d++) acc += __ldg(&wb[d]) * s_sw[il][d];
        int i = i0 + il;
        g_mod[b * CIN + i] = (acc * LIN_COEF + sb[i]) * CONV_COEF;
    } else if (bid < 288) {
        __shared__ float sc[32][289];
        int q = bid - 32;
        int i0 = (q & 15) * 32;
        int o0 = (q >> 4) * 32;
        for (int idx = threadIdx.x; idx < 32 * 288; idx += 256) {
            int r = idx / 288, cc = idx - r * 288;
            sc[r][cc] = cw[(size_t)(o0 + r) * 4608 + i0 * 9 + cc];
        }
        __syncthreads();
        for (int idx = threadIdx.x; idx < 1024; idx += 256) {
            int oi = idx & 31, ii = idx >> 5;
            float s = 0.f;
#pragma unroll
            for (int tap = 0; tap < 9; tap++) {
                float v = sc[oi][ii * 9 + tap];
                s += v * v;
            }
            g_wsqT[(i0 + ii) * COUT + o0 + oi] = s;
        }
    } else {
        int o = bid - 288;
        for (int i = threadIdx.x; i < CIN; i += 256) {
            const float* p = cw + ((size_t)o * CIN + i) * 9;
#pragma unroll
            for (int tap = 0; tap < 9; tap++) {
                g_wh[((size_t)tap * COUT + o) * CIN + i] =
                    __float2half_rn(p[tap]);
            }
        }
    }
}

// ============================================================
// KP2: sigma_inv (bid<16) + x modulate/transpose/fp16 (bid<8208)
// ============================================================
__global__ __launch_bounds__(512) void kp2(const float* __restrict__ x)
{
    __shared__ float t[64][65];
    int bid = blockIdx.x;
    if (bid < 16) {
        float* m2 = &t[0][0];
        int b = bid, o = threadIdx.x;
        for (int i = threadIdx.x; i < CIN; i += 512) {
            float m = g_mod[b * CIN + i];
            m2[i] = m * m;
        }
        __syncthreads();
        float s = 0.f;
        for (int i = 0; i < CIN; i++) s += m2[i] * g_wsqT[i * COUT + o];
        g_sig[b * COUT + o] = 1.0f / sqrtf(s + 1e-8f);
        return;
    }
    int q = bid - 16;
    int p0 = (q & 63) * 64;
    int i0 = ((q >> 6) & 7) * 64;
    int b  = q >> 9;
    for (int idx = threadIdx.x; idx < 1024; idx += 512) {
        int ii = idx >> 4, pp = (idx & 15) * 4;
        float4 v = *(const float4*)&x[((size_t)b * CIN + i0 + ii) * NPIX + p0 + pp];
        float m = g_mod[b * CIN + i0 + ii];
        t[ii][pp]     = v.x * m;
        t[ii][pp + 1] = v.y * m;
        t[ii][pp + 2] = v.z * m;
        t[ii][pp + 3] = v.w * m;
    }
    __syncthreads();
    for (int idx = threadIdx.x; idx < 1024; idx += 512) {
        int pp = idx >> 4, ii = (idx & 15) * 4;
        __half2 h0 = __floats2half2_rn(t[ii][pp],     t[ii + 1][pp]);
        __half2 h1 = __floats2half2_rn(t[ii + 2][pp], t[ii + 3][pp]);
        uint2 u;
        u.x = *(uint32_t*)&h0;
        u.y = *(uint32_t*)&h1;
        *(uint2*)&g_xh[((size_t)b * NPIX + p0 + pp) * CIN + i0 + ii] = u;
    }
}

// ============================================================
// K6: conv, single-pass fp16 HMMA GEMM, 16x16 pixel tiles.
// CTA 128oc x 256px, 512 thr, warp grid 4(M)x4(N), warp tile 32oc x 64px.
// K chunk = 128 ic (2 panels of 64), 4 chunks x 9 taps = 36 stages.
// A: 32KB/stage double-buffered.
// B: halo 18x18 x 128ic (83KB) double-buffered, prefetched as 8 ~10KB
//    SLICES, one per tap stage, merged into that stage's commit group.
// -> exactly ONE in-flight group per stage; uniform wg0 at stage top.
// smem 231424, regs 128, 1 CTA/SM.
// ============================================================
#define BH_DIM  18
#define BH_PX   (BH_DIM * BH_DIM)        // 324
#define BPNL    (BH_PX * 128)            // 41472 per panel
#define BBUF    (2 * BPNL)               // 82944 per buffer
#define A_STG   32768                    // 2 panels x 16KB
#define B_OFF   (2 * A_STG)              // 65536
#define DSMEM   (B_OFF + 2 * BBUF)       // 231424
#define BSLICE  41                       // halo px per slice (8 slices: 7x41+37)

#define MMA_F16(c, a, b0, b1)                                                \
    asm volatile("mma.sync.aligned.m16n8k16.row.col.f32.f16.f16.f32 "        \
        "{%0,%1,%2,%3}, {%4,%5,%6,%7}, {%8,%9}, {%0,%1,%2,%3};"              \
        : "+f"((c)[0]), "+f"((c)[1]), "+f"((c)[2]), "+f"((c)[3])             \
        : "r"((a)[0]), "r"((a)[1]), "r"((a)[2]), "r"((a)[3]),                \
          "r"(b0), "r"(b1))

#define LDSM4(r, addr)                                                       \
    asm volatile("ldmatrix.sync.aligned.m8n8.x4.shared.b16 "                 \
        "{%0,%1,%2,%3}, [%4];"                                               \
        : "=r"((r)[0]), "=r"((r)[1]), "=r"((r)[2]), "=r"((r)[3])             \
        : "r"(addr))

__global__ __launch_bounds__(512, 1) void k_conv_hmma(
    const float* __restrict__ noise, const float* __restrict__ scale_noise,
    const float* __restrict__ bias, float* __restrict__ out)
{
    extern __shared__ __align__(1024) char dsm[];
    uint32_t sbase = smem_u32(dsm);

    int tid = threadIdx.x;
    int lane = tid & 31, wid = tid >> 5;
    int wm = wid >> 2, wn = wid & 3;
    int b    = blockIdx.z;
    int oc0  = blockIdx.x * 128;
    int pr0  = (blockIdx.y >> 2) * 16;    // tile row origin
    int pc0  = (blockIdx.y & 3) * 16;     // tile col origin

    // A ldmatrix lane components
    int selA = ((lane >> 4) & 1) * 16;
    uint32_t rbA[2], mkA[2];
#pragma unroll
    for (int mt = 0; mt < 2; mt++) {
        int row = wm * 32 + mt * 16 + (lane & 15);
        rbA[mt] = row * 128;
        mkA[mt] = (uint32_t)(row & 7) << 4;
    }
    // B lane pixel decomposition (16x16 tile)
    int selB = ((lane >> 3) & 1) * 16;
    int irB[4], icB;
    icB = (lane & 7) + ((lane >> 4) & 1) * 8;          // col within tile
#pragma unroll
    for (int j = 0; j < 4; j++) irB[j] = wn * 4 + j;   // row within tile

    float acc[2][8][4];
#pragma unroll
    for (int mt = 0; mt < 2; mt++)
#pragma unroll
        for (int nt = 0; nt < 8; nt++)
#pragma unroll
            for (int q = 0; q < 4; q++) acc[mt][nt][q] = 0.f;

    // A stage loads (no commit): 128 rows x 256B (2 panels of 64 ic)
    auto load_A = [&](int tapv, int chv, int buf) {
#pragma unroll
        for (int k = 0; k < 4; k++) {
            int idx = tid + k * 512;
            int panel = idx >> 10;
            int rem = idx & 1023;
            int row = rem >> 3, cb = rem & 7;
            const __half* g = g_wh +
                ((size_t)tapv * COUT + oc0 + row) * CIN +
                chv * 128 + panel * 64 + cb * 8;
            uint32_t d = sbase + buf * A_STG + panel * 16384 +
                         (uint32_t)(row * 128) +
                         (uint32_t)((cb * 16) ^ ((row & 7) << 4));
            asm volatile("cp.async.cg.shared.global [%0], [%1], 16;"
                         :: "r"(d), "l"(g));
        }
    };

    // B halo slice (no commit): pixels [p0s, p1s) of the 324-px halo
    auto load_B_slice = [&](int chv, int buf, int p0s, int p1s) {
        int cnt = (p1s - p0s) * 16;
        for (int idx = tid; idx < cnt; idx += 512) {
            int px = p0s + (idx >> 4);
            int qq = idx & 15;
            int panel = qq >> 3, cb = qq & 7;
            int hrow = px / BH_DIM;
            int hcol = px - hrow * BH_DIM;
            int r = pr0 - 1 + hrow;
            int c = pc0 - 1 + hcol;
            int ok = ((unsigned)r < Hs) && ((unsigned)c < Ws);
            const __half* g = g_xh +
                ((size_t)b * NPIX + (ok ? r * Ws + c : 0)) * CIN +
                chv * 128 + panel * 64 + cb * 8;
            uint32_t d = sbase + B_OFF + buf * BBUF + panel * BPNL +
                         (uint32_t)(px * 128) +
                         (uint32_t)((cb * 16) ^ ((px & 7) << 4));
            int sz = ok ? 16 : 0;
            asm volatile("cp.async.cg.shared.global [%0], [%1], 16, %2;"
                         :: "r"(d), "l"(g), "r"(sz));
        }
    };

    // prologue: full B(0) + A(0), one group
    load_B_slice(0, 0, 0, BH_PX);
    load_A(0, 0, 0);
    asm volatile("cp.async.commit_group;");

    int s = 0;
    for (int ch = 0; ch < 4; ch++) {
        for (int tap = 0; tap < 9; tap++, s++) {
            asm volatile("cp.async.wait_group 0;");
            __syncthreads();

            // issue next loads as ONE group: A(s+1) + slice 'tap' of B(ch+1)
            if (s < 35) {
                int s1 = s + 1;
                load_A(s1 % 9, s1 / 9, s1 & 1);
            }
            if (tap < 8 && ch < 3) {
                int p0s = tap * BSLICE;
                int p1s = (tap == 7) ? BH_PX : p0s + BSLICE;
                load_B_slice(ch + 1, (ch + 1) & 1, p0s, p1s);
            }
            asm volatile("cp.async.commit_group;");

            // ---- compute stage s ----
            uint32_t abuf = sbase + (s & 1) * A_STG;
            uint32_t bbuf = sbase + B_OFF + (ch & 1) * BBUF;
            int dy = tap / 3 - 1, dx = tap % 3 - 1;
            uint32_t rowB[4], mskB[4];
#pragma unroll
            for (int j = 0; j < 4; j++) {
                int rp = (irB[j] + 1 + dy) * BH_DIM + icB + 1 + dx;
                rowB[j] = (uint32_t)(rp * 128);
                mskB[j] = (uint32_t)(rp & 7) << 4;
            }

#pragma unroll
            for (int kk = 0; kk < 8; kk++) {
                int pn  = kk >> 2;
                int col = (kk & 3) * 32;
                uint32_t aF[2][4];
#pragma unroll
                for (int mt = 0; mt < 2; mt++) {
                    uint32_t a = abuf + pn * 16384 + rbA[mt] +
                                 (uint32_t)((col + selA) ^ mkA[mt]);
                    LDSM4(aF[mt], a);
                }
                uint32_t bF[4][4];
#pragma unroll
                for (int j = 0; j < 4; j++) {
                    uint32_t a = bbuf + pn * BPNL + rowB[j] +
                                 (uint32_t)((col + selB) ^ mskB[j]);
                    LDSM4(bF[j], a);
                }
#pragma unroll
                for (int mt = 0; mt < 2; mt++)
#pragma unroll
                    for (int nt = 0; nt < 8; nt++) {
                        int j = nt >> 1, lo = (nt & 1) * 2;
                        MMA_F16(acc[mt][nt], aF[mt], bF[j][lo], bF[j][lo + 1]);
                    }
            }
        }
    }

    // ---------------- epilogue ----------------
    float sn = __ldg(scale_noise);
#pragma unroll
    for (int mt = 0; mt < 2; mt++) {
        int oc_lo = oc0 + wm * 32 + mt * 16 + (lane >> 2);
        float sg0 = g_sig[b * COUT + oc_lo];
        float sg1 = g_sig[b * COUT + oc_lo + 8];
        float bi0 = __ldg(&bias[oc_lo]);
        float bi1 = __ldg(&bias[oc_lo + 8]);
#pragma unroll
        for (int nt = 0; nt < 8; nt++) {
            int n = wn * 64 + nt * 8 + (lane & 3) * 2;
            int row = pr0 + (n >> 4);
            int col = pc0 + (n & 15);
            int p = row * Ws + col;
            float2 nz = *(const float2*)&noise[(size_t)b * NPIX + p];
            float n0 = sn * nz.x, n1 = sn * nz.y;

            float v0 = acc[mt][nt][0] * sg0 + n0 + bi0;
            float v1 = acc[mt][nt][1] * sg0 + n1 + bi0;
            float v2 = acc[mt][nt][2] * sg1 + n0 + bi1;
            float v3 = acc[mt][nt][3] * sg1 + n1 + bi1;
            v0 = v0 < 0.f ? 0.2f * v0 : v0;
            v1 = v1 < 0.f ? 0.2f * v1 : v1;
            v2 = v2 < 0.f ? 0.2f * v2 : v2;
            v3 = v3 < 0.f ? 0.2f * v3 : v3;

            *(float2*)&out[((size_t)(b * COUT + oc_lo)) * NPIX + p] =
                make_float2(v0, v1);
            *(float2*)&out[((size_t)(b * COUT + oc_lo + 8)) * NPIX + p] =
                make_float2(v2, v3);
        }
    }
}

// ============================================================
// launch: x, w, noise, style_w, style_b, conv_w, scale_noise, bias
// 3 launches: kp1, kp2(+sigma), conv
// ============================================================
extern "C" void kernel_launch(void* const* d_in, const int* in_sizes, int n_in,
                              void* d_out, int out_size)
{
    const float* x           = (const float*)d_in[0];
    const float* w           = (const float*)d_in[1];
    const float* noise       = (const float*)d_in[2];
    const float* style_w     = (const float*)d_in[3];
    const float* style_b     = (const float*)d_in[4];
    const float* conv_w      = (const float*)d_in[5];
    const float* scale_noise = (const float*)d_in[6];
    const float* bias        = (const float*)d_in[7];
    float* out = (float*)d_out;

    cudaFuncSetAttribute(k_conv_hmma,
                         cudaFuncAttributeMaxDynamicSharedMemorySize, DSMEM);

    kp1<<<800, 256>>>(w, style_w, style_b, conv_w);
    kp2<<<8208, 512>>>(x);
    k_conv_hmma<<<dim3(4, 16, B_), 512, DSMEM>>>(noise, scale_noise, bias, out);
}

// round 16
// speedup vs baseline: 1.0238x; 1.0238x over previous
#include <cuda_runtime.h>
#include <cuda_fp16.h>
#include <cstdint>

#define B_    16
#define CIN   512
#define COUT  512
#define DLAT  512
#define Hs    64
#define Ws    64
#define NPIX  (Hs*Ws)

#define LIN_COEF  0.04419417382415922f    // 1/sqrt(512)
#define CONV_COEF 0.014731391274719742f   // 1/sqrt(512*9)

// ---------------- device scratch (no allocation allowed) ----------------
__device__ float g_mod[B_ * CIN];
__device__ float g_sig[B_ * COUT];
__device__ float g_wsqT[CIN * COUT];               // [i][o]
__device__ __half g_xh[(size_t)B_ * NPIX * CIN];   // NHWC, fp16(x*mod)
__device__ __half g_wh[9 * COUT * CIN];            // [tap][o][i] fp16

__device__ __forceinline__ uint32_t smem_u32(const void* p) {
    uint32_t a;
    asm("{ .reg .u64 t; cvta.to.shared.u64 t, %1; cvt.u32.u64 %0, t; }"
        : "=r"(a) : "l"(p));
    return a;
}

// ============================================================
// KP1: style (bid<32) + fused wsq/w->fp16 tile (bid 32..288)
// Each tile block stages cw[32 o][32 i][9 tap] in smem ONCE, then
// emits both g_wsqT and g_wh from it.
// ============================================================
__global__ __launch_bounds__(256) void kp1(
    const float* __restrict__ w, const float* __restrict__ sw,
    const float* __restrict__ sb, const float* __restrict__ cw)
{
    int bid = blockIdx.x;
    if (bid < 32) {
        __shared__ float s_sw[16][DLAT + 1];
        int i0 = bid * 16;
        for (int idx = threadIdx.x; idx < 16 * DLAT; idx += 256) {
            int r = idx / DLAT, d = idx % DLAT;
            s_sw[r][d] = sw[(i0 + r) * DLAT + d];
        }
        __syncthreads();
        int t = threadIdx.x;
        int b = t >> 4, il = t & 15;
        const float* wb = w + b * DLAT;
        float acc = 0.f;
        for (int d = 0; d < DLAT; d++) acc += __ldg(&wb[d]) * s_sw[il][d];
        int i = i0 + il;
        g_mod[b * CIN + i] = (acc * LIN_COEF + sb[i]) * CONV_COEF;
        return;
    }
    __shared__ float sc[32][289];
    int q = bid - 32;
    int i0 = (q & 15) * 32;
    int o0 = (q >> 4) * 32;
    for (int idx = threadIdx.x; idx < 32 * 288; idx += 256) {
        int r = idx / 288, cc = idx - r * 288;
        sc[r][cc] = cw[(size_t)(o0 + r) * 4608 + i0 * 9 + cc];
    }
    __syncthreads();
    // wsq reduction
    for (int idx = threadIdx.x; idx < 1024; idx += 256) {
        int oi = idx & 31, ii = idx >> 5;
        float s = 0.f;
#pragma unroll
        for (int tap = 0; tap < 9; tap++) {
            float v = sc[oi][ii * 9 + tap];
            s += v * v;
        }
        g_wsqT[(i0 + ii) * COUT + o0 + oi] = s;
    }
    // fp16 weight emission: (tap, oi, ii), ii fastest -> contiguous 64B stores
    for (int idx = threadIdx.x; idx < 32 * 32 * 9; idx += 256) {
        int ii = idx & 31;
        int rest = idx >> 5;            // 0..287
        int oi = rest & 31;
        int tap = rest >> 5;            // 0..8
        g_wh[((size_t)tap * COUT + o0 + oi) * CIN + i0 + ii] =
            __float2half_rn(sc[oi][ii * 9 + tap]);
    }
}

// ============================================================
// KP2: sigma_inv (bid<16) + x modulate/transpose/fp16 (bid<8208)
// ============================================================
__global__ __launch_bounds__(512) void kp2(const float* __restrict__ x)
{
    __shared__ float t[64][65];
    int bid = blockIdx.x;
    if (bid < 16) {
        float* m2 = &t[0][0];
        int b = bid, o = threadIdx.x;
        for (int i = threadIdx.x; i < CIN; i += 512) {
            float m = g_mod[b * CIN + i];
            m2[i] = m * m;
        }
        __syncthreads();
        float s = 0.f;
        for (int i = 0; i < CIN; i++) s += m2[i] * g_wsqT[i * COUT + o];
        g_sig[b * COUT + o] = 1.0f / sqrtf(s + 1e-8f);
        return;
    }
    int q = bid - 16;
    int p0 = (q & 63) * 64;
    int i0 = ((q >> 6) & 7) * 64;
    int b  = q >> 9;
    for (int idx = threadIdx.x; idx < 1024; idx += 512) {
        int ii = idx >> 4, pp = (idx & 15) * 4;
        float4 v = *(const float4*)&x[((size_t)b * CIN + i0 + ii) * NPIX + p0 + pp];
        float m = g_mod[b * CIN + i0 + ii];
        t[ii][pp]     = v.x * m;
        t[ii][pp + 1] = v.y * m;
        t[ii][pp + 2] = v.z * m;
        t[ii][pp + 3] = v.w * m;
    }
    __syncthreads();
    for (int idx = threadIdx.x; idx < 1024; idx += 512) {
        int pp = idx >> 4, ii = (idx & 15) * 4;
        __half2 h0 = __floats2half2_rn(t[ii][pp],     t[ii + 1][pp]);
        __half2 h1 = __floats2half2_rn(t[ii + 2][pp], t[ii + 3][pp]);
        uint2 u;
        u.x = *(uint32_t*)&h0;
        u.y = *(uint32_t*)&h1;
        *(uint2*)&g_xh[((size_t)b * NPIX + p0 + pp) * CIN + i0 + ii] = u;
    }
}

// ============================================================
// K6: conv, single-pass fp16 HMMA GEMM, 16x16 pixel tiles.
// (R14 champion, verbatim)
// CTA 128oc x 256px, 512 thr, warp grid 4(M)x4(N), warp tile 32oc x 64px.
// K chunk = 128 ic (2 panels of 64), 4 chunks x 9 taps = 36 stages.
// A: 32KB/stage double-buffered; B: halo 18x18 x 128ic (83KB) double-buffered.
// smem 231424, regs 128, 1 CTA/SM.
// Wait: tap1 (ch<3) -> wg1 (A done, B(ch+1) rides); else wg0.
// ============================================================
#define BH_DIM  18
#define BH_PX   (BH_DIM * BH_DIM)        // 324
#define BPNL    (BH_PX * 128)            // 41472 per panel
#define BBUF    (2 * BPNL)               // 82944 per buffer
#define A_STG   32768                    // 2 panels x 16KB
#define B_OFF   (2 * A_STG)              // 65536
#define DSMEM   (B_OFF + 2 * BBUF)       // 231424

#define MMA_F16(c, a, b0, b1)                                                \
    asm volatile("mma.sync.aligned.m16n8k16.row.col.f32.f16.f16.f32 "        \
        "{%0,%1,%2,%3}, {%4,%5,%6,%7}, {%8,%9}, {%0,%1,%2,%3};"              \
        : "+f"((c)[0]), "+f"((c)[1]), "+f"((c)[2]), "+f"((c)[3])             \
        : "r"((a)[0]), "r"((a)[1]), "r"((a)[2]), "r"((a)[3]),                \
          "r"(b0), "r"(b1))

#define LDSM4(r, addr)                                                       \
    asm volatile("ldmatrix.sync.aligned.m8n8.x4.shared.b16 "                 \
        "{%0,%1,%2,%3}, [%4];"                                               \
        : "=r"((r)[0]), "=r"((r)[1]), "=r"((r)[2]), "=r"((r)[3])             \
        : "r"(addr))

__global__ __launch_bounds__(512, 1) void k_conv_hmma(
    const float* __restrict__ noise, const float* __restrict__ scale_noise,
    const float* __restrict__ bias, float* __restrict__ out)
{
    extern __shared__ __align__(1024) char dsm[];
    uint32_t sbase = smem_u32(dsm);

    int tid = threadIdx.x;
    int lane = tid & 31, wid = tid >> 5;
    int wm = wid >> 2, wn = wid & 3;
    int b    = blockIdx.z;
    int oc0  = blockIdx.x * 128;
    int pr0  = (blockIdx.y >> 2) * 16;    // tile row origin
    int pc0  = (blockIdx.y & 3) * 16;     // tile col origin

    // A ldmatrix lane components
    int selA = ((lane >> 4) & 1) * 16;
    uint32_t rbA[2], mkA[2];
#pragma unroll
    for (int mt = 0; mt < 2; mt++) {
        int row = wm * 32 + mt * 16 + (lane & 15);
        rbA[mt] = row * 128;
        mkA[mt] = (uint32_t)(row & 7) << 4;
    }
    // B lane pixel decomposition (16x16 tile)
    int selB = ((lane >> 3) & 1) * 16;
    int irB[4], icB;
    icB = (lane & 7) + ((lane >> 4) & 1) * 8;          // col within tile
#pragma unroll
    for (int j = 0; j < 4; j++) irB[j] = wn * 4 + j;   // row within tile

    float acc[2][8][4];
#pragma unroll
    for (int mt = 0; mt < 2; mt++)
#pragma unroll
        for (int nt = 0; nt < 8; nt++)
#pragma unroll
            for (int q = 0; q < 4; q++) acc[mt][nt][q] = 0.f;

    // A stage: 128 rows x 256B (2 panels of 64 ic)
    auto load_A = [&](int tapv, int chv, int buf) {
#pragma unroll
        for (int k = 0; k < 4; k++) {
            int idx = tid + k * 512;
            int panel = idx >> 10;
            int rem = idx & 1023;
            int row = rem >> 3, cb = rem & 7;
            const __half* g = g_wh +
                ((size_t)tapv * COUT + oc0 + row) * CIN +
                chv * 128 + panel * 64 + cb * 8;
            uint32_t d = sbase + buf * A_STG + panel * 16384 +
                         (uint32_t)(row * 128) +
                         (uint32_t)((cb * 16) ^ ((row & 7) << 4));
            asm volatile("cp.async.cg.shared.global [%0], [%1], 16;"
                         :: "r"(d), "l"(g));
        }
        asm volatile("cp.async.commit_group;");
    };

    // B halo: 324 px x 256B (2 panels)
    auto load_B = [&](int chv, int buf) {
        for (int idx = tid; idx < BH_PX * 16; idx += 512) {
            int px = idx >> 4;
            int qq = idx & 15;
            int panel = qq >> 3, cb = qq & 7;
            int hrow = px / BH_DIM;
            int hcol = px - hrow * BH_DIM;
            int r = pr0 - 1 + hrow;
            int c = pc0 - 1 + hcol;
            int ok = ((unsigned)r < Hs) && ((unsigned)c < Ws);
            const __half* g = g_xh +
                ((size_t)b * NPIX + (ok ? r * Ws + c : 0)) * CIN +
                chv * 128 + panel * 64 + cb * 8;
            uint32_t d = sbase + B_OFF + buf * BBUF + panel * BPNL +
                         (uint32_t)(px * 128) +
                         (uint32_t)((cb * 16) ^ ((px & 7) << 4));
            int sz = ok ? 16 : 0;
            asm volatile("cp.async.cg.shared.global [%0], [%1], 16, %2;"
                         :: "r"(d), "l"(g), "r"(sz));
        }
        asm volatile("cp.async.commit_group;");
    };

    // prologue: B(0), A(stage 0)
    load_B(0, 0);
    load_A(0, 0, 0);

    int s = 0;
    for (int ch = 0; ch < 4; ch++) {
        for (int tap = 0; tap < 9; tap++, s++) {
            if (tap == 1 && ch < 3)
                asm volatile("cp.async.wait_group 1;");   // A(s) done; B(ch+1) rides
            else
                asm volatile("cp.async.wait_group 0;");
            __syncthreads();

            if (s < 35) {
                int s1 = s + 1;
                load_A(s1 % 9, s1 / 9, s1 & 1);
            }
            if (tap == 0 && ch < 3) load_B(ch + 1, (ch + 1) & 1);

            // ---- compute stage s ----
            uint32_t abuf = sbase + (s & 1) * A_STG;
            uint32_t bbuf = sbase + B_OFF + (ch & 1) * BBUF;
            int dy = tap / 3 - 1, dx = tap % 3 - 1;
            uint32_t rowB[4], mskB[4];
#pragma unroll
            for (int j = 0; j < 4; j++) {
                int rp = (irB[j] + 1 + dy) * BH_DIM + icB + 1 + dx;
                rowB[j] = (uint32_t)(rp * 128);
                mskB[j] = (uint32_t)(rp & 7) << 4;
            }

#pragma unroll
            for (int kk = 0; kk < 8; kk++) {
                int pn  = kk >> 2;
                int col = (kk & 3) * 32;
                uint32_t aF[2][4];
#pragma unroll
                for (int mt = 0; mt < 2; mt++) {
                    uint32_t a = abuf + pn * 16384 + rbA[mt] +
                                 (uint32_t)((col + selA) ^ mkA[mt]);
                    LDSM4(aF[mt], a);
                }
                uint32_t bF[4][4];
#pragma unroll
                for (int j = 0; j < 4; j++) {
                    uint32_t a = bbuf + pn * BPNL + rowB[j] +
                                 (uint32_t)((col + selB) ^ mskB[j]);
                    LDSM4(bF[j], a);
                }
#pragma unroll
                for (int mt = 0; mt < 2; mt++)
#pragma unroll
                    for (int nt = 0; nt < 8; nt++) {
                        int j = nt >> 1, lo = (nt & 1) * 2;
                        MMA_F16(acc[mt][nt], aF[mt], bF[j][lo], bF[j][lo + 1]);
                    }
            }
        }
    }

    // ---------------- epilogue ----------------
    float sn = __ldg(scale_noise);
#pragma unroll
    for (int mt = 0; mt < 2; mt++) {
        int oc_lo = oc0 + wm * 32 + mt * 16 + (lane >> 2);
        float sg0 = g_sig[b * COUT + oc_lo];
        float sg1 = g_sig[b * COUT + oc_lo + 8];
        float bi0 = __ldg(&bias[oc_lo]);
        float bi1 = __ldg(&bias[oc_lo + 8]);
#pragma unroll
        for (int nt = 0; nt < 8; nt++) {
            int n = wn * 64 + nt * 8 + (lane & 3) * 2;
            int row = pr0 + (n >> 4);
            int col = pc0 + (n & 15);
            int p = row * Ws + col;
            float2 nz = *(const float2*)&noise[(size_t)b * NPIX + p];
            float n0 = sn * nz.x, n1 = sn * nz.y;

            float v0 = acc[mt][nt][0] * sg0 + n0 + bi0;
            float v1 = acc[mt][nt][1] * sg0 + n1 + bi0;
            float v2 = acc[mt][nt][2] * sg1 + n0 + bi1;
            float v3 = acc[mt][nt][3] * sg1 + n1 + bi1;
            v0 = v0 < 0.f ? 0.2f * v0 : v0;
            v1 = v1 < 0.f ? 0.2f * v1 : v1;
            v2 = v2 < 0.f ? 0.2f * v2 : v2;
            v3 = v3 < 0.f ? 0.2f * v3 : v3;

            *(float2*)&out[((size_t)(b * COUT + oc_lo)) * NPIX + p] =
                make_float2(v0, v1);
            *(float2*)&out[((size_t)(b * COUT + oc_lo + 8)) * NPIX + p] =
                make_float2(v2, v3);
        }
    }
}

// ============================================================
// launch: x, w, noise, style_w, style_b, conv_w, scale_noise, bias
// 3 launches: kp1, kp2(+sigma), conv
// ============================================================
extern "C" void kernel_launch(void* const* d_in, const int* in_sizes, int n_in,
                              void* d_out, int out_size)
{
    const float* x           = (const float*)d_in[0];
    const float* w           = (const float*)d_in[1];
    const float* noise       = (const float*)d_in[2];
    const float* style_w     = (const float*)d_in[3];
    const float* style_b     = (const float*)d_in[4];
    const float* conv_w      = (const float*)d_in[5];
    const float* scale_noise = (const float*)d_in[6];
    const float* bias        = (const float*)d_in[7];
    float* out = (float*)d_out;

    cudaFuncSetAttribute(k_conv_hmma,
                         cudaFuncAttributeMaxDynamicSharedMemorySize, DSMEM);

    kp1<<<288, 256>>>(w, style_w, style_b, conv_w);
    kp2<<<8208, 512>>>(x);
    k_conv_hmma<<<dim3(4, 16, B_), 512, DSMEM>>>(noise, scale_noise, bias, out);
}

// round 17
// speedup vs baseline: 1.0249x; 1.0011x over previous
#include <cuda_runtime.h>
#include <cuda_fp16.h>
#include <cstdint>

#define B_    16
#define CIN   512
#define COUT  512
#define DLAT  512
#define Hs    64
#define Ws    64
#define NPIX  (Hs*Ws)

#define LIN_COEF  0.04419417382415922f    // 1/sqrt(512)
#define CONV_COEF 0.014731391274719742f   // 1/sqrt(512*9)

// ---------------- device scratch (no allocation allowed) ----------------
__device__ float g_mod[B_ * CIN];
__device__ float g_sig[B_ * COUT];
__device__ float g_wsqT[CIN * COUT];               // [i][o]
__device__ __half g_xh[(size_t)B_ * NPIX * CIN];   // NHWC, fp16(x*mod)
__device__ __half g_wh[9 * COUT * CIN];            // [tap][o][i] fp16

__device__ __forceinline__ uint32_t smem_u32(const void* p) {
    uint32_t a;
    asm("{ .reg .u64 t; cvta.to.shared.u64 t, %1; cvt.u32.u64 %0, t; }"
        : "=r"(a) : "l"(p));
    return a;
}

// ============================================================
// KP1: style (bid<32) + fused wsq/w->fp16 tile (bid 32..288)
// Tile staging uses float4 global loads (72 per 32-float-row of 9-tap data)
// with scalar smem stores to keep the conflict-free stride-289 layout.
// ============================================================
__global__ __launch_bounds__(256) void kp1(
    const float* __restrict__ w, const float* __restrict__ sw,
    const float* __restrict__ sb, const float* __restrict__ cw)
{
    int bid = blockIdx.x;
    if (bid < 32) {
        __shared__ float s_sw[16][DLAT + 1];
        int i0 = bid * 16;
        for (int idx = threadIdx.x; idx < 16 * DLAT; idx += 256) {
            int r = idx / DLAT, d = idx % DLAT;
            s_sw[r][d] = sw[(i0 + r) * DLAT + d];
        }
        __syncthreads();
        int t = threadIdx.x;
        int b = t >> 4, il = t & 15;
        const float* wb = w + b * DLAT;
        float acc = 0.f;
        for (int d = 0; d < DLAT; d++) acc += __ldg(&wb[d]) * s_sw[il][d];
        int i = i0 + il;
        g_mod[b * CIN + i] = (acc * LIN_COEF + sb[i]) * CONV_COEF;
        return;
    }
    __shared__ float sc[32][289];
    int q = bid - 32;
    int i0 = (q & 15) * 32;
    int o0 = (q >> 4) * 32;
    // stage cw[32 o][32 i][9 tap] via float4 loads (2304 vec4 / block)
    for (int idx = threadIdx.x; idx < 32 * 72; idx += 256) {
        int r = idx / 72, cc = (idx - r * 72) * 4;
        float4 v = *(const float4*)&cw[(size_t)(o0 + r) * 4608 + i0 * 9 + cc];
        sc[r][cc]     = v.x;
        sc[r][cc + 1] = v.y;
        sc[r][cc + 2] = v.z;
        sc[r][cc + 3] = v.w;
    }
    __syncthreads();
    // wsq reduction
    for (int idx = threadIdx.x; idx < 1024; idx += 256) {
        int oi = idx & 31, ii = idx >> 5;
        float s = 0.f;
#pragma unroll
        for (int tap = 0; tap < 9; tap++) {
            float v = sc[oi][ii * 9 + tap];
            s += v * v;
        }
        g_wsqT[(i0 + ii) * COUT + o0 + oi] = s;
    }
    // fp16 weight emission: (tap, oi, ii), ii fastest -> contiguous 64B stores
    for (int idx = threadIdx.x; idx < 32 * 32 * 9; idx += 256) {
        int ii = idx & 31;
        int rest = idx >> 5;
        int oi = rest & 31;
        int tap = rest >> 5;
        g_wh[((size_t)tap * COUT + o0 + oi) * CIN + i0 + ii] =
            __float2half_rn(sc[oi][ii * 9 + tap]);
    }
}

// ============================================================
// KP2: sigma_inv (bid<16) + x modulate/transpose/fp16 (bid<8208)
// ============================================================
__global__ __launch_bounds__(512) void kp2(const float* __restrict__ x)
{
    __shared__ float t[64][65];
    int bid = blockIdx.x;
    if (bid < 16) {
        float* m2 = &t[0][0];
        int b = bid, o = threadIdx.x;
        for (int i = threadIdx.x; i < CIN; i += 512) {
            float m = g_mod[b * CIN + i];
            m2[i] = m * m;
        }
        __syncthreads();
        float s = 0.f;
        for (int i = 0; i < CIN; i++) s += m2[i] * g_wsqT[i * COUT + o];
        g_sig[b * COUT + o] = 1.0f / sqrtf(s + 1e-8f);
        return;
    }
    int q = bid - 16;
    int p0 = (q & 63) * 64;
    int i0 = ((q >> 6) & 7) * 64;
    int b  = q >> 9;
    for (int idx = threadIdx.x; idx < 1024; idx += 512) {
        int ii = idx >> 4, pp = (idx & 15) * 4;
        float4 v = *(const float4*)&x[((size_t)b * CIN + i0 + ii) * NPIX + p0 + pp];
        float m = g_mod[b * CIN + i0 + ii];
        t[ii][pp]     = v.x * m;
        t[ii][pp + 1] = v.y * m;
        t[ii][pp + 2] = v.z * m;
        t[ii][pp + 3] = v.w * m;
    }
    __syncthreads();
    for (int idx = threadIdx.x; idx < 1024; idx += 512) {
        int pp = idx >> 4, ii = (idx & 15) * 4;
        __half2 h0 = __floats2half2_rn(t[ii][pp],     t[ii + 1][pp]);
        __half2 h1 = __floats2half2_rn(t[ii + 2][pp], t[ii + 3][pp]);
        uint2 u;
        u.x = *(uint32_t*)&h0;
        u.y = *(uint32_t*)&h1;
        *(uint2*)&g_xh[((size_t)b * NPIX + p0 + pp) * CIN + i0 + ii] = u;
    }
}

// ============================================================
// K6: conv, single-pass fp16 HMMA GEMM, 16x16 pixel tiles.
// (R14/R16 champion, verbatim)
// CTA 128oc x 256px, 512 thr, warp grid 4(M)x4(N), warp tile 32oc x 64px.
// K chunk = 128 ic (2 panels of 64), 4 chunks x 9 taps = 36 stages.
// A: 32KB/stage double-buffered; B: halo 18x18 x 128ic (83KB) double-buffered.
// smem 231424, regs 128, 1 CTA/SM.
// Wait: tap1 (ch<3) -> wg1 (A done, B(ch+1) rides); else wg0.
// ============================================================
#define BH_DIM  18
#define BH_PX   (BH_DIM * BH_DIM)        // 324
#define BPNL    (BH_PX * 128)            // 41472 per panel
#define BBUF    (2 * BPNL)               // 82944 per buffer
#define A_STG   32768                    // 2 panels x 16KB
#define B_OFF   (2 * A_STG)              // 65536
#define DSMEM   (B_OFF + 2 * BBUF)       // 231424

#define MMA_F16(c, a, b0, b1)                                                \
    asm volatile("mma.sync.aligned.m16n8k16.row.col.f32.f16.f16.f32 "        \
        "{%0,%1,%2,%3}, {%4,%5,%6,%7}, {%8,%9}, {%0,%1,%2,%3};"              \
        : "+f"((c)[0]), "+f"((c)[1]), "+f"((c)[2]), "+f"((c)[3])             \
        : "r"((a)[0]), "r"((a)[1]), "r"((a)[2]), "r"((a)[3]),                \
          "r"(b0), "r"(b1))

#define LDSM4(r, addr)                                                       \
    asm volatile("ldmatrix.sync.aligned.m8n8.x4.shared.b16 "                 \
        "{%0,%1,%2,%3}, [%4];"                                               \
        : "=r"((r)[0]), "=r"((r)[1]), "=r"((r)[2]), "=r"((r)[3])             \
        : "r"(addr))

__global__ __launch_bounds__(512, 1) void k_conv_hmma(
    const float* __restrict__ noise, const float* __restrict__ scale_noise,
    const float* __restrict__ bias, float* __restrict__ out)
{
    extern __shared__ __align__(1024) char dsm[];
    uint32_t sbase = smem_u32(dsm);

    int tid = threadIdx.x;
    int lane = tid & 31, wid = tid >> 5;
    int wm = wid >> 2, wn = wid & 3;
    int b    = blockIdx.z;
    int oc0  = blockIdx.x * 128;
    int pr0  = (blockIdx.y >> 2) * 16;    // tile row origin
    int pc0  = (blockIdx.y & 3) * 16;     // tile col origin

    // A ldmatrix lane components
    int selA = ((lane >> 4) & 1) * 16;
    uint32_t rbA[2], mkA[2];
#pragma unroll
    for (int mt = 0; mt < 2; mt++) {
        int row = wm * 32 + mt * 16 + (lane & 15);
        rbA[mt] = row * 128;
        mkA[mt] = (uint32_t)(row & 7) << 4;
    }
    // B lane pixel decomposition (16x16 tile)
    int selB = ((lane >> 3) & 1) * 16;
    int irB[4], icB;
    icB = (lane & 7) + ((lane >> 4) & 1) * 8;          // col within tile
#pragma unroll
    for (int j = 0; j < 4; j++) irB[j] = wn * 4 + j;   // row within tile

    float acc[2][8][4];
#pragma unroll
    for (int mt = 0; mt < 2; mt++)
#pragma unroll
        for (int nt = 0; nt < 8; nt++)
#pragma unroll
            for (int q = 0; q < 4; q++) acc[mt][nt][q] = 0.f;

    // A stage: 128 rows x 256B (2 panels of 64 ic)
    auto load_A = [&](int tapv, int chv, int buf) {
#pragma unroll
        for (int k = 0; k < 4; k++) {
            int idx = tid + k * 512;
            int panel = idx >> 10;
            int rem = idx & 1023;
            int row = rem >> 3, cb = rem & 7;
            const __half* g = g_wh +
                ((size_t)tapv * COUT + oc0 + row) * CIN +
                chv * 128 + panel * 64 + cb * 8;
            uint32_t d = sbase + buf * A_STG + panel * 16384 +
                         (uint32_t)(row * 128) +
                         (uint32_t)((cb * 16) ^ ((row & 7) << 4));
            asm volatile("cp.async.cg.shared.global [%0], [%1], 16;"
                         :: "r"(d), "l"(g));
        }
        asm volatile("cp.async.commit_group;");
    };

    // B halo: 324 px x 256B (2 panels)
    auto load_B = [&](int chv, int buf) {
        for (int idx = tid; idx < BH_PX * 16; idx += 512) {
            int px = idx >> 4;
            int qq = idx & 15;
            int panel = qq >> 3, cb = qq & 7;
            int hrow = px / BH_DIM;
            int hcol = px - hrow * BH_DIM;
            int r = pr0 - 1 + hrow;
            int c = pc0 - 1 + hcol;
            int ok = ((unsigned)r < Hs) && ((unsigned)c < Ws);
            const __half* g = g_xh +
                ((size_t)b * NPIX + (ok ? r * Ws + c : 0)) * CIN +
                chv * 128 + panel * 64 + cb * 8;
            uint32_t d = sbase + B_OFF + buf * BBUF + panel * BPNL +
                         (uint32_t)(px * 128) +
                         (uint32_t)((cb * 16) ^ ((px & 7) << 4));
            int sz = ok ? 16 : 0;
            asm volatile("cp.async.cg.shared.global [%0], [%1], 16, %2;"
                         :: "r"(d), "l"(g), "r"(sz));
        }
        asm volatile("cp.async.commit_group;");
    };

    // prologue: B(0), A(stage 0)
    load_B(0, 0);
    load_A(0, 0, 0);

    int s = 0;
    for (int ch = 0; ch < 4; ch++) {
        for (int tap = 0; tap < 9; tap++, s++) {
            if (tap == 1 && ch < 3)
                asm volatile("cp.async.wait_group 1;");   // A(s) done; B(ch+1) rides
            else
                asm volatile("cp.async.wait_group 0;");
            __syncthreads();

            if (s < 35) {
                int s1 = s + 1;
                load_A(s1 % 9, s1 / 9, s1 & 1);
            }
            if (tap == 0 && ch < 3) load_B(ch + 1, (ch + 1) & 1);

            // ---- compute stage s ----
            uint32_t abuf = sbase + (s & 1) * A_STG;
            uint32_t bbuf = sbase + B_OFF + (ch & 1) * BBUF;
            int dy = tap / 3 - 1, dx = tap % 3 - 1;
            uint32_t rowB[4], mskB[4];
#pragma unroll
            for (int j = 0; j < 4; j++) {
                int rp = (irB[j] + 1 + dy) * BH_DIM + icB + 1 + dx;
                rowB[j] = (uint32_t)(rp * 128);
                mskB[j] = (uint32_t)(rp & 7) << 4;
            }

#pragma unroll
            for (int kk = 0; kk < 8; kk++) {
                int pn  = kk >> 2;
                int col = (kk & 3) * 32;
                uint32_t aF[2][4];
#pragma unroll
                for (int mt = 0; mt < 2; mt++) {
                    uint32_t a = abuf + pn * 16384 + rbA[mt] +
                                 (uint32_t)((col + selA) ^ mkA[mt]);
                    LDSM4(aF[mt], a);
                }
                uint32_t bF[4][4];
#pragma unroll
                for (int j = 0; j < 4; j++) {
                    uint32_t a = bbuf + pn * BPNL + rowB[j] +
                                 (uint32_t)((col + selB) ^ mskB[j]);
                    LDSM4(bF[j], a);
                }
#pragma unroll
                for (int mt = 0; mt < 2; mt++)
#pragma unroll
                    for (int nt = 0; nt < 8; nt++) {
                        int j = nt >> 1, lo = (nt & 1) * 2;
                        MMA_F16(acc[mt][nt], aF[mt], bF[j][lo], bF[j][lo + 1]);
                    }
            }
        }
    }

    // ---------------- epilogue ----------------
    float sn = __ldg(scale_noise);
#pragma unroll
    for (int mt = 0; mt < 2; mt++) {
        int oc_lo = oc0 + wm * 32 + mt * 16 + (lane >> 2);
        float sg0 = g_sig[b * COUT + oc_lo];
        float sg1 = g_sig[b * COUT + oc_lo + 8];
        float bi0 = __ldg(&bias[oc_lo]);
        float bi1 = __ldg(&bias[oc_lo + 8]);
#pragma unroll
        for (int nt = 0; nt < 8; nt++) {
            int n = wn * 64 + nt * 8 + (lane & 3) * 2;
            int row = pr0 + (n >> 4);
            int col = pc0 + (n & 15);
            int p = row * Ws + col;
            float2 nz = *(const float2*)&noise[(size_t)b * NPIX + p];
            float n0 = sn * nz.x, n1 = sn * nz.y;

            float v0 = acc[mt][nt][0] * sg0 + n0 + bi0;
            float v1 = acc[mt][nt][1] * sg0 + n1 + bi0;
            float v2 = acc[mt][nt][2] * sg1 + n0 + bi1;
            float v3 = acc[mt][nt][3] * sg1 + n1 + bi1;
            v0 = v0 < 0.f ? 0.2f * v0 : v0;
            v1 = v1 < 0.f ? 0.2f * v1 : v1;
            v2 = v2 < 0.f ? 0.2f * v2 : v2;
            v3 = v3 < 0.f ? 0.2f * v3 : v3;

            *(float2*)&out[((size_t)(b * COUT + oc_lo)) * NPIX + p] =
                make_float2(v0, v1);
            *(float2*)&out[((size_t)(b * COUT + oc_lo + 8)) * NPIX + p] =
                make_float2(v2, v3);
        }
    }
}

// ============================================================
// launch: x, w, noise, style_w, style_b, conv_w, scale_noise, bias
// 3 launches: kp1, kp2(+sigma), conv
// ============================================================
extern "C" void kernel_launch(void* const* d_in, const int* in_sizes, int n_in,
                              void* d_out, int out_size)
{
    const float* x           = (const float*)d_in[0];
    const float* w           = (const float*)d_in[1];
    const float* noise       = (const float*)d_in[2];
    const float* style_w     = (const float*)d_in[3];
    const float* style_b     = (const float*)d_in[4];
    const float* conv_w      = (const float*)d_in[5];
    const float* scale_noise = (const float*)d_in[6];
    const float* bias        = (const float*)d_in[7];
    float* out = (float*)d_out;

    cudaFuncSetAttribute(k_conv_hmma,
                         cudaFuncAttributeMaxDynamicSharedMemorySize, DSMEM);

    kp1<<<288, 256>>>(w, style_w, style_b, conv_w);
    kp2<<<8208, 512>>>(x);
    k_conv_hmma<<<dim3(4, 16, B_), 512, DSMEM>>>(noise, scale_noise, bias, out);
}